// round 15
// baseline (speedup 1.0000x reference)
#include <cuda_runtime.h>
#include <cuda_bf16.h>
#include <cuda_fp16.h>
#include <math.h>

#define N_NODES 100000
#define N_EDGES 640000
#define IN_FEATS 256
#define HEADS 4
#define OUT_FEATS 32
#define HD (HEADS * OUT_FEATS)   // 128
#define NEG_SLOPE 0.2f

#define GEMM_BLOCKS ((N_NODES + 127) / 128)      // 782
#define SCAN_BLOCKS 98                           // ceil(100000/1024)

// GEMM smem geometry (floats)
#define AS_STRIDE 36
#define BS_STRIDE 132
#define AS_STAGE (128 * AS_STRIDE)
#define BS_STAGE (32 * BS_STRIDE)
#define GEMM_SMEM_BYTES ((2 * AS_STAGE + 2 * BS_STAGE) * 4)   // 70656 B

// ---------------- scratch (no allocs allowed) ----------------
__device__ float    g_ft [(size_t)N_NODES * HD];     // fp32 ft (el/er + exactness)
__device__ __half   g_fth[(size_t)N_NODES * HD];     // fp16 shadow for gathers
__device__ float    g_el[N_NODES * HEADS];
__device__ float    g_er[N_NODES * HEADS];
__device__ float    g_e [(size_t)N_EDGES * HEADS];   // exp(logit), CSR order
__device__ float    g_wt[IN_FEATS * HD];             // tf32-rounded, permuted W
__device__ int      g_pool[N_NODES + 256];           // counts + scan states
__device__ int      g_offsets[N_NODES + 1];
__device__ int      g_cursor[N_NODES];
__device__ unsigned long long g_csr[N_EDGES];        // (src<<32)|edge_id

#define G_COUNTS (g_pool)
#define G_STATE  ((unsigned long long*)(g_pool + N_NODES))

// ---------------- helpers ----------------
__device__ __forceinline__ unsigned tf32_bits(float x) {
    unsigned u;
    asm("cvt.rna.tf32.f32 %0, %1;" : "=r"(u) : "f"(x));
    return u;
}
__device__ __forceinline__ float to_tf32(float x) {
    return __uint_as_float(tf32_bits(x));
}
__device__ __forceinline__ void cp_async16(unsigned smem, const void* gmem,
                                           int src_bytes) {
    asm volatile("cp.async.cg.shared.global [%0], [%1], 16, %2;"
                 :: "r"(smem), "l"(gmem), "r"(src_bytes));
}
__device__ __forceinline__ void cp_commit() {
    asm volatile("cp.async.commit_group;");
}
__device__ __forceinline__ void mma_tf32(float* d, const unsigned* a,
                                         unsigned b0, unsigned b1) {
    asm volatile(
        "mma.sync.aligned.m16n8k8.row.col.f32.tf32.tf32.f32 "
        "{%0,%1,%2,%3}, {%4,%5,%6,%7}, {%8,%9}, {%0,%1,%2,%3};"
        : "+f"(d[0]), "+f"(d[1]), "+f"(d[2]), "+f"(d[3])
        : "r"(a[0]), "r"(a[1]), "r"(a[2]), "r"(a[3]), "r"(b0), "r"(b1));
}

// ---------------- scan body (256 threads, 1024 items/block) ------------------
__device__ void scan_body(int b, int* smi) {
    const int t = threadIdx.x;
    const int lane = t & 31, w = t >> 5;
    const int base = b * 1024 + t * 4;

    int v0 = 0, v1 = 0, v2 = 0, v3 = 0;
    if (base + 3 < N_NODES) {
        int4 q = *(const int4*)(G_COUNTS + base);
        v0 = q.x; v1 = q.y; v2 = q.z; v3 = q.w;
    } else {
        if (base + 0 < N_NODES) v0 = G_COUNTS[base + 0];
        if (base + 1 < N_NODES) v1 = G_COUNTS[base + 1];
        if (base + 2 < N_NODES) v2 = G_COUNTS[base + 2];
        if (base + 3 < N_NODES) v3 = G_COUNTS[base + 3];
    }
    int tsum = v0 + v1 + v2 + v3;
    int x = tsum;
#pragma unroll
    for (int o = 1; o < 32; o <<= 1) {
        int u = __shfl_up_sync(0xffffffffu, x, o);
        if (lane >= o) x += u;
    }
    if (lane == 31) smi[w] = x;
    __syncthreads();
    if (t < 8) {
        int acc = 0;
        for (int j = 0; j <= t; j++) acc += smi[j];
        smi[t + 16] = acc;
    }
    __syncthreads();
    int warp_off = (w > 0) ? smi[16 + w - 1] : 0;
    int total = smi[16 + 7];

    if (t == 0) {
        unsigned long long* st = G_STATE;
        int excl = 0;
        if (b == 0) {
            __threadfence();
            atomicExch(&st[0], (2ULL << 32) | (unsigned)total);
        } else {
            __threadfence();
            atomicExch(&st[b], (1ULL << 32) | (unsigned)total);
            for (int j = b - 1; j >= 0;) {
                unsigned long long sv;
                do { sv = atomicAdd(&st[j], 0ULL); } while ((sv >> 32) == 0ULL);
                excl += (int)(sv & 0xffffffffULL);
                if ((sv >> 32) == 2ULL) break;
                j--;
            }
            __threadfence();
            atomicExch(&st[b], (2ULL << 32) | (unsigned)(excl + total));
        }
        smi[8] = excl;
    }
    __syncthreads();
    int pre = smi[8] + warp_off + (x - tsum);

    int o0 = pre, o1 = pre + v0, o2 = pre + v0 + v1, o3 = pre + v0 + v1 + v2;
    if (base + 3 < N_NODES) {
        *(int4*)(g_offsets + base) = make_int4(o0, o1, o2, o3);
        *(int4*)(g_cursor  + base) = make_int4(o0, o1, o2, o3);
    } else {
        if (base + 0 < N_NODES) { g_offsets[base+0] = o0; g_cursor[base+0] = o0; }
        if (base + 1 < N_NODES) { g_offsets[base+1] = o1; g_cursor[base+1] = o1; }
        if (base + 2 < N_NODES) { g_offsets[base+2] = o2; g_cursor[base+2] = o2; }
        if (base + 3 < N_NODES) { g_offsets[base+3] = o3; g_cursor[base+3] = o3; }
    }
    if (b == 0 && t == 0) g_offsets[N_NODES] = N_EDGES;
}

// ---- GEMM (TF32 MMA, cp.async 2-stage) + el/er + fp16 shadow + scan --------
__global__ __launch_bounds__(256, 2) void gemm_tf32_kernel(
    const float* __restrict__ A, const float* __restrict__ B,
    const float* __restrict__ attn_l, const float* __restrict__ attn_r,
    float* __restrict__ C)
{
    extern __shared__ float sm[];
    if (blockIdx.x >= GEMM_BLOCKS) {
        scan_body(blockIdx.x - GEMM_BLOCKS, (int*)sm);
        return;
    }
    const unsigned sm_u32 = (unsigned)__cvta_generic_to_shared(sm);
    const int tid  = threadIdx.x;
    const int warp = tid >> 5, lane = tid & 31;
    const int wm = warp >> 1, wn = warp & 1;
    const int g = lane >> 2, c = lane & 3;
    const int blockM = blockIdx.x * 128;

    float acc[2][8][4];
#pragma unroll
    for (int i = 0; i < 2; i++)
#pragma unroll
        for (int j = 0; j < 8; j++)
#pragma unroll
            for (int r = 0; r < 4; r++) acc[i][j][r] = 0.0f;

    auto load_stage = [&](int stage, int k0) {
        unsigned as_base = sm_u32 + (unsigned)(stage * AS_STAGE) * 4u;
        unsigned bs_base = sm_u32 + (unsigned)((2 * AS_STAGE) + stage * BS_STAGE) * 4u;
#pragma unroll
        for (int it = 0; it < 4; it++) {
            int f   = tid + it * 256;
            int row = f >> 3;
            int seg = f & 7;
            int grow = blockM + row;
            int sz = (grow < N_NODES) ? 16 : 0;
            cp_async16(as_base + (unsigned)(row * AS_STRIDE + seg * 4) * 4u,
                       A + (size_t)grow * IN_FEATS + k0 + seg * 4, sz);
        }
#pragma unroll
        for (int it = 0; it < 4; it++) {
            int f  = tid + it * 256;
            int kr = f >> 5;
            int cs = (f & 31) * 4;
            cp_async16(bs_base + (unsigned)(kr * BS_STRIDE + cs) * 4u,
                       B + (size_t)(k0 + kr) * HD + cs, 16);
        }
    };

    load_stage(0, 0);
    cp_commit();

    for (int i = 0; i < 8; i++) {
        const int stage = i & 1;
        if (i < 7) {
            load_stage(stage ^ 1, (i + 1) * 32);
            cp_commit();
            asm volatile("cp.async.wait_group 1;");
        } else {
            asm volatile("cp.async.wait_group 0;");
        }
        __syncthreads();

        const float* As_s = sm + stage * AS_STAGE;
        const float* Bs_s = sm + 2 * AS_STAGE + stage * BS_STAGE;

#pragma unroll
        for (int ks = 0; ks < 4; ks++) {
            const int kb = ks * 8;
            unsigned afrag[2][4];
#pragma unroll
            for (int ii = 0; ii < 2; ii++) {
                int r = wm * 32 + ii * 16;
                afrag[ii][0] = tf32_bits(As_s[(r + g    ) * AS_STRIDE + kb + c    ]);
                afrag[ii][1] = tf32_bits(As_s[(r + g + 8) * AS_STRIDE + kb + c    ]);
                afrag[ii][2] = tf32_bits(As_s[(r + g    ) * AS_STRIDE + kb + c + 4]);
                afrag[ii][3] = tf32_bits(As_s[(r + g + 8) * AS_STRIDE + kb + c + 4]);
            }
            const float4* b0p = (const float4*)(Bs_s + (kb + c    ) * BS_STRIDE
                                                + g * 16 + wn * 8);
            const float4* b1p = (const float4*)(Bs_s + (kb + c + 4) * BS_STRIDE
                                                + g * 16 + wn * 8);
            float4 b0a = b0p[0], b0b = b0p[1];
            float4 b1a = b1p[0], b1b = b1p[1];
            const float b0v[8] = {b0a.x, b0a.y, b0a.z, b0a.w,
                                  b0b.x, b0b.y, b0b.z, b0b.w};
            const float b1v[8] = {b1a.x, b1a.y, b1a.z, b1a.w,
                                  b1b.x, b1b.y, b1b.z, b1b.w};
#pragma unroll
            for (int j = 0; j < 8; j++) {
                unsigned b0 = __float_as_uint(b0v[j]);
                unsigned b1 = __float_as_uint(b1v[j]);
                mma_tf32(acc[0][j], afrag[0], b0, b1);
                mma_tf32(acc[1][j], afrag[1], b0, b1);
            }
        }
        __syncthreads();
    }

    // epilogue 1: store ft (fp32) + fp16 shadow for agg gathers
#pragma unroll
    for (int i = 0; i < 2; i++) {
        int r0 = blockM + wm * 32 + i * 16 + g;
#pragma unroll
        for (int j = 0; j < 8; j++) {
            int cc = wn * 64 + j * 8 + c * 2;
            if (r0 < N_NODES) {
                *(float2*)(C + (size_t)r0 * HD + cc) =
                    make_float2(acc[i][j][0], acc[i][j][1]);
                *(__half2*)(g_fth + (size_t)r0 * HD + cc) =
                    __floats2half2_rn(acc[i][j][0], acc[i][j][1]);
            }
            if (r0 + 8 < N_NODES) {
                *(float2*)(C + (size_t)(r0 + 8) * HD + cc) =
                    make_float2(acc[i][j][2], acc[i][j][3]);
                *(__half2*)(g_fth + (size_t)(r0 + 8) * HD + cc) =
                    __floats2half2_rn(acc[i][j][2], acc[i][j][3]);
            }
        }
    }

    // epilogue 2: el/er
    float elp[4][2], erp[4][2];
#pragma unroll
    for (int rs = 0; rs < 4; rs++)
#pragma unroll
        for (int hl = 0; hl < 2; hl++) { elp[rs][hl] = 0.f; erp[rs][hl] = 0.f; }
#pragma unroll
    for (int i = 0; i < 2; i++)
#pragma unroll
        for (int j = 0; j < 8; j++)
#pragma unroll
            for (int r = 0; r < 4; r++) {
                int col = wn * 64 + j * 8 + c * 2 + (r & 1);
                float wl = __ldg(attn_l + col);
                float wr = __ldg(attn_r + col);
                int rs = i * 2 + (r >> 1);
                elp[rs][j >> 2] += acc[i][j][r] * wl;
                erp[rs][j >> 2] += acc[i][j][r] * wr;
            }
#pragma unroll
    for (int rs = 0; rs < 4; rs++)
#pragma unroll
        for (int hl = 0; hl < 2; hl++) {
#pragma unroll
            for (int o = 1; o <= 2; o <<= 1) {
                elp[rs][hl] += __shfl_xor_sync(0xffffffffu, elp[rs][hl], o);
                erp[rs][hl] += __shfl_xor_sync(0xffffffffu, erp[rs][hl], o);
            }
        }
    if (c == 0) {
#pragma unroll
        for (int rs = 0; rs < 4; rs++) {
            int row = blockM + wm * 32 + (rs >> 1) * 16 + (rs & 1) * 8 + g;
            if (row < N_NODES) {
#pragma unroll
                for (int hl = 0; hl < 2; hl++) {
                    int h = wn * 2 + hl;
                    g_el[row * HEADS + h] = elp[rs][hl];
                    g_er[row * HEADS + h] = erp[rs][hl];
                }
            }
        }
    }
}

// -------- histogram (int4) + fused tf32 round + PERMUTE of W ----------------
__global__ void hist_kernel(const int* __restrict__ dst,
                            const float* __restrict__ W) {
    int i = blockIdx.x * blockDim.x + threadIdx.x;
    if (i < (IN_FEATS * HD) / 4) {
        float4 v = ((const float4*)W)[i];
        int k = (i * 4) / HD;
        int n = (i * 4) % HD;
        float vv[4] = {to_tf32(v.x), to_tf32(v.y), to_tf32(v.z), to_tf32(v.w)};
#pragma unroll
        for (int q = 0; q < 4; q++) {
            int nn = n + q;
            int p = (nn & 7) * 16 + ((nn >> 6) & 1) * 8 + ((nn >> 3) & 7);
            g_wt[k * HD + p] = vv[q];
        }
    }
    if (i >= N_EDGES / 4) return;
    int4 d = ((const int4*)dst)[i];
    atomicAdd(&G_COUNTS[d.x], 1);
    atomicAdd(&G_COUNTS[d.y], 1);
    atomicAdd(&G_COUNTS[d.z], 1);
    atomicAdd(&G_COUNTS[d.w], 1);
}

// ---- CSR scatter + softmax numerator (after gemm: el/er ready) --------------
__global__ void scatter_kernel(const int* __restrict__ src,
                               const int* __restrict__ dst) {
    int e = blockIdx.x * blockDim.x + threadIdx.x;
    if (e >= N_EDGES) return;
    int s = src[e], d = dst[e];
    float4 el4 = *(const float4*)(g_el + (size_t)s * HEADS);
    float4 er4 = *(const float4*)(g_er + (size_t)d * HEADS);
    float4 v;
    v.x = el4.x + er4.x; v.y = el4.y + er4.y;
    v.z = el4.z + er4.z; v.w = el4.w + er4.w;
    v.x = v.x > 0.f ? v.x : NEG_SLOPE * v.x;
    v.y = v.y > 0.f ? v.y : NEG_SLOPE * v.y;
    v.z = v.z > 0.f ? v.z : NEG_SLOPE * v.z;
    v.w = v.w > 0.f ? v.w : NEG_SLOPE * v.w;
    float4 ex4;
    ex4.x = __expf(v.x); ex4.y = __expf(v.y);
    ex4.z = __expf(v.z); ex4.w = __expf(v.w);
    int pos = atomicAdd(&g_cursor[d], 1);
    g_csr[pos] = ((unsigned long long)(unsigned)s << 32) | (unsigned)e;
    *(float4*)(g_e + (size_t)pos * HEADS) = ex4;
}

// ---- aggregation (round-11 structure): one warp per node --------------------
// Gathers from the fp16 shadow (256B rows -> half the L2 traffic); accumulates
// in fp32. ex/denominator path unchanged (fp32).
__global__ __launch_bounds__(256, 6) void agg_fused_kernel(
    float* __restrict__ rst, float* __restrict__ a_out, int has_a)
{
    __shared__ float ex_s[8][32][4];   // [warp][edge-in-chunk][head]
    int warp = (blockIdx.x * blockDim.x + threadIdx.x) >> 5;
    int lane = threadIdx.x & 31;
    int wlocal = (threadIdx.x >> 5);
    if (warp >= N_NODES) return;
    const int h = lane >> 3;
    const int p0 = g_offsets[warp];
    const int p1 = g_offsets[warp + 1];
    const int deg = p1 - p0;

    if (deg == 0) {
        *(float4*)(rst + (size_t)warp * HD + lane * 4) =
            make_float4(0.f, 0.f, 0.f, 0.f);
        return;
    }

    float4 acc = make_float4(0.f, 0.f, 0.f, 0.f);
    float denh = 0.0f;
    const uint2* fhl = (const uint2*)g_fth + lane;  // lane's 4 halves of a row

    float4 ex4 = make_float4(0.f, 0.f, 0.f, 0.f);   // my edge, last chunk
    int eid = 0;

    for (int base = p0; base < p1; base += 32) {
        int p = base + lane;
        ex4 = make_float4(0.f, 0.f, 0.f, 0.f);
        int s = 0;
        if (p < p1) {
            unsigned long long pk = g_csr[p];
            s = (int)(pk >> 32);
            eid = (int)(unsigned)(pk & 0xffffffffULL);
            ex4 = *(const float4*)(g_e + (size_t)p * HEADS);   // coalesced
        }

        __syncwarp();
        *(float4*)&ex_s[wlocal][lane][0] = ex4;
        __syncwarp();

        int cnt = min(p1 - base, 32);
        for (int q0 = 0; q0 < cnt; q0 += 4) {
            int m = cnt - q0;
            uint2 u0, u1, u2, u3;
            int sq;
            // issue all gathers first (MLP=4); 8B/lane, coalesced 256B rows
            sq = __shfl_sync(0xffffffffu, s, q0);
            u0 = fhl[(size_t)(unsigned)sq * 32u];
            if (m > 1) { sq = __shfl_sync(0xffffffffu, s, q0 + 1);
                         u1 = fhl[(size_t)(unsigned)sq * 32u]; }
            if (m > 2) { sq = __shfl_sync(0xffffffffu, s, q0 + 2);
                         u2 = fhl[(size_t)(unsigned)sq * 32u]; }
            if (m > 3) { sq = __shfl_sync(0xffffffffu, s, q0 + 3);
                         u3 = fhl[(size_t)(unsigned)sq * 32u]; }
            {
                float e0 = ex_s[wlocal][q0][h];
                denh += e0;
                float2 a0 = __half22float2(*(__half2*)&u0.x);
                float2 a1 = __half22float2(*(__half2*)&u0.y);
                acc.x += e0 * a0.x; acc.y += e0 * a0.y;
                acc.z += e0 * a1.x; acc.w += e0 * a1.y;
            }
            if (m > 1) {
                float e1 = ex_s[wlocal][q0 + 1][h];
                denh += e1;
                float2 a0 = __half22float2(*(__half2*)&u1.x);
                float2 a1 = __half22float2(*(__half2*)&u1.y);
                acc.x += e1 * a0.x; acc.y += e1 * a0.y;
                acc.z += e1 * a1.x; acc.w += e1 * a1.y;
            }
            if (m > 2) {
                float e2 = ex_s[wlocal][q0 + 2][h];
                denh += e2;
                float2 a0 = __half22float2(*(__half2*)&u2.x);
                float2 a1 = __half22float2(*(__half2*)&u2.y);
                acc.x += e2 * a0.x; acc.y += e2 * a0.y;
                acc.z += e2 * a1.x; acc.w += e2 * a1.y;
            }
            if (m > 3) {
                float e3 = ex_s[wlocal][q0 + 3][h];
                denh += e3;
                float2 a0 = __half22float2(*(__half2*)&u3.x);
                float2 a1 = __half22float2(*(__half2*)&u3.y);
                acc.x += e3 * a0.x; acc.y += e3 * a0.y;
                acc.z += e3 * a1.x; acc.w += e3 * a1.y;
            }
        }
    }

    float rdh = 1.0f / denh;
    acc.x *= rdh; acc.y *= rdh; acc.z *= rdh; acc.w *= rdh;
    *(float4*)(rst + (size_t)warp * HD + lane * 4) = acc;

    if (has_a) {
        float4 rd4;
        rd4.x = __shfl_sync(0xffffffffu, rdh, 0);
        rd4.y = __shfl_sync(0xffffffffu, rdh, 8);
        rd4.z = __shfl_sync(0xffffffffu, rdh, 16);
        rd4.w = __shfl_sync(0xffffffffu, rdh, 24);
        if (deg <= 32) {
            int p = p0 + lane;
            if (p < p1) {
                float4 a4 = make_float4(ex4.x * rd4.x, ex4.y * rd4.y,
                                        ex4.z * rd4.z, ex4.w * rd4.w);
                *(float4*)(a_out + (size_t)eid * HEADS) = a4;
            }
        } else {
            for (int p = p0 + lane; p < p1; p += 32) {
                float4 e4 = *(const float4*)(g_e + (size_t)p * HEADS);
                int e = (int)(unsigned)(g_csr[p] & 0xffffffffULL);
                float4 a4 = make_float4(e4.x * rd4.x, e4.y * rd4.y,
                                        e4.z * rd4.z, e4.w * rd4.w);
                *(float4*)(a_out + (size_t)e * HEADS) = a4;
            }
        }
    }
}

// ---------------- launch ------------------------------------------------------
extern "C" void kernel_launch(void* const* d_in, const int* in_sizes, int n_in,
                              void* d_out, int out_size)
{
    const float* feat   = (const float*)d_in[0];
    const float* W      = (const float*)d_in[1];
    const float* attn_l = (const float*)d_in[2];
    const float* attn_r = (const float*)d_in[3];
    const int*   src    = (const int*)d_in[4];
    const int*   dst    = (const int*)d_in[5];
    float* out = (float*)d_out;

    const int rst_elems = N_NODES * HD;
    const int has_a = (out_size >= rst_elems + N_EDGES * HEADS) ? 1 : 0;
    float* a_out = out + rst_elems;

    float* ft_dev;   cudaGetSymbolAddress((void**)&ft_dev, g_ft);
    float* wt_dev;   cudaGetSymbolAddress((void**)&wt_dev, g_wt);
    int*   pool_dev; cudaGetSymbolAddress((void**)&pool_dev, g_pool);

    cudaFuncSetAttribute(gemm_tf32_kernel,
                         cudaFuncAttributeMaxDynamicSharedMemorySize,
                         GEMM_SMEM_BYTES);

    cudaMemsetAsync(pool_dev, 0, (N_NODES + 256) * sizeof(int));

    hist_kernel<<<(N_EDGES / 4 + 255) / 256, 256>>>(dst, W);

    gemm_tf32_kernel<<<GEMM_BLOCKS + SCAN_BLOCKS, 256, GEMM_SMEM_BYTES>>>(
        feat, wt_dev, attn_l, attn_r, ft_dev);

    scatter_kernel<<<(N_EDGES + 255) / 256, 256>>>(src, dst);

    agg_fused_kernel<<<(N_NODES * 32 + 255) / 256, 256>>>(out, a_out, has_a);
}

// round 16
// speedup vs baseline: 1.0497x; 1.0497x over previous
#include <cuda_runtime.h>
#include <cuda_bf16.h>
#include <cuda_fp16.h>
#include <math.h>

#define N_NODES 100000
#define N_EDGES 640000
#define IN_FEATS 256
#define HEADS 4
#define OUT_FEATS 32
#define HD (HEADS * OUT_FEATS)   // 128
#define NEG_SLOPE 0.2f

#define GEMM_BLOCKS ((N_NODES + 127) / 128)      // 782
#define SCAN_BLOCKS 98                           // ceil(100000/1024)

// GEMM smem geometry (floats)
#define AS_STRIDE 36
#define BS_STRIDE 132
#define AS_STAGE (128 * AS_STRIDE)
#define BS_STAGE (32 * BS_STRIDE)
#define GEMM_SMEM_BYTES ((2 * AS_STAGE + 2 * BS_STAGE) * 4)   // 70656 B

// ---------------- scratch (no allocs allowed) ----------------
__device__ __half   g_fth[(size_t)N_NODES * HD];     // fp16 ft (the ONLY ft copy)
__device__ float    g_el[N_NODES * HEADS];
__device__ float    g_er[N_NODES * HEADS];
__device__ float    g_e [(size_t)N_EDGES * HEADS];   // exp(logit), CSR order
__device__ float    g_wt[IN_FEATS * HD];             // tf32-rounded, permuted W
__device__ int      g_pool[N_NODES + 256];           // counts + scan states
__device__ int      g_offsets[N_NODES + 1];
__device__ int      g_cursor[N_NODES];
__device__ unsigned long long g_csr[N_EDGES];        // (src<<32)|edge_id

#define G_COUNTS (g_pool)
#define G_STATE  ((unsigned long long*)(g_pool + N_NODES))

// ---------------- helpers ----------------
__device__ __forceinline__ unsigned tf32_bits(float x) {
    unsigned u;
    asm("cvt.rna.tf32.f32 %0, %1;" : "=r"(u) : "f"(x));
    return u;
}
__device__ __forceinline__ float to_tf32(float x) {
    return __uint_as_float(tf32_bits(x));
}
__device__ __forceinline__ void cp_async16(unsigned smem, const void* gmem,
                                           int src_bytes) {
    asm volatile("cp.async.cg.shared.global [%0], [%1], 16, %2;"
                 :: "r"(smem), "l"(gmem), "r"(src_bytes));
}
__device__ __forceinline__ void cp_commit() {
    asm volatile("cp.async.commit_group;");
}
__device__ __forceinline__ void mma_tf32(float* d, const unsigned* a,
                                         unsigned b0, unsigned b1) {
    asm volatile(
        "mma.sync.aligned.m16n8k8.row.col.f32.tf32.tf32.f32 "
        "{%0,%1,%2,%3}, {%4,%5,%6,%7}, {%8,%9}, {%0,%1,%2,%3};"
        : "+f"(d[0]), "+f"(d[1]), "+f"(d[2]), "+f"(d[3])
        : "r"(a[0]), "r"(a[1]), "r"(a[2]), "r"(a[3]), "r"(b0), "r"(b1));
}

// ---------------- scan body (256 threads, 1024 items/block) ------------------
__device__ void scan_body(int b, int* smi) {
    const int t = threadIdx.x;
    const int lane = t & 31, w = t >> 5;
    const int base = b * 1024 + t * 4;

    int v0 = 0, v1 = 0, v2 = 0, v3 = 0;
    if (base + 3 < N_NODES) {
        int4 q = *(const int4*)(G_COUNTS + base);
        v0 = q.x; v1 = q.y; v2 = q.z; v3 = q.w;
    } else {
        if (base + 0 < N_NODES) v0 = G_COUNTS[base + 0];
        if (base + 1 < N_NODES) v1 = G_COUNTS[base + 1];
        if (base + 2 < N_NODES) v2 = G_COUNTS[base + 2];
        if (base + 3 < N_NODES) v3 = G_COUNTS[base + 3];
    }
    int tsum = v0 + v1 + v2 + v3;
    int x = tsum;
#pragma unroll
    for (int o = 1; o < 32; o <<= 1) {
        int u = __shfl_up_sync(0xffffffffu, x, o);
        if (lane >= o) x += u;
    }
    if (lane == 31) smi[w] = x;
    __syncthreads();
    if (t < 8) {
        int acc = 0;
        for (int j = 0; j <= t; j++) acc += smi[j];
        smi[t + 16] = acc;
    }
    __syncthreads();
    int warp_off = (w > 0) ? smi[16 + w - 1] : 0;
    int total = smi[16 + 7];

    if (t == 0) {
        unsigned long long* st = G_STATE;
        int excl = 0;
        if (b == 0) {
            __threadfence();
            atomicExch(&st[0], (2ULL << 32) | (unsigned)total);
        } else {
            __threadfence();
            atomicExch(&st[b], (1ULL << 32) | (unsigned)total);
            for (int j = b - 1; j >= 0;) {
                unsigned long long sv;
                do { sv = atomicAdd(&st[j], 0ULL); } while ((sv >> 32) == 0ULL);
                excl += (int)(sv & 0xffffffffULL);
                if ((sv >> 32) == 2ULL) break;
                j--;
            }
            __threadfence();
            atomicExch(&st[b], (2ULL << 32) | (unsigned)(excl + total));
        }
        smi[8] = excl;
    }
    __syncthreads();
    int pre = smi[8] + warp_off + (x - tsum);

    int o0 = pre, o1 = pre + v0, o2 = pre + v0 + v1, o3 = pre + v0 + v1 + v2;
    if (base + 3 < N_NODES) {
        *(int4*)(g_offsets + base) = make_int4(o0, o1, o2, o3);
        *(int4*)(g_cursor  + base) = make_int4(o0, o1, o2, o3);
    } else {
        if (base + 0 < N_NODES) { g_offsets[base+0] = o0; g_cursor[base+0] = o0; }
        if (base + 1 < N_NODES) { g_offsets[base+1] = o1; g_cursor[base+1] = o1; }
        if (base + 2 < N_NODES) { g_offsets[base+2] = o2; g_cursor[base+2] = o2; }
        if (base + 3 < N_NODES) { g_offsets[base+3] = o3; g_cursor[base+3] = o3; }
    }
    if (b == 0 && t == 0) g_offsets[N_NODES] = N_EDGES;
}

// ---- GEMM (TF32 MMA, cp.async 2-stage) + el/er + fp16-only ft + scan -------
__global__ __launch_bounds__(256, 2) void gemm_tf32_kernel(
    const float* __restrict__ A, const float* __restrict__ B,
    const float* __restrict__ attn_l, const float* __restrict__ attn_r)
{
    extern __shared__ float sm[];
    if (blockIdx.x >= GEMM_BLOCKS) {
        scan_body(blockIdx.x - GEMM_BLOCKS, (int*)sm);
        return;
    }
    const unsigned sm_u32 = (unsigned)__cvta_generic_to_shared(sm);
    const int tid  = threadIdx.x;
    const int warp = tid >> 5, lane = tid & 31;
    const int wm = warp >> 1, wn = warp & 1;
    const int g = lane >> 2, c = lane & 3;
    const int blockM = blockIdx.x * 128;

    float acc[2][8][4];
#pragma unroll
    for (int i = 0; i < 2; i++)
#pragma unroll
        for (int j = 0; j < 8; j++)
#pragma unroll
            for (int r = 0; r < 4; r++) acc[i][j][r] = 0.0f;

    auto load_stage = [&](int stage, int k0) {
        unsigned as_base = sm_u32 + (unsigned)(stage * AS_STAGE) * 4u;
        unsigned bs_base = sm_u32 + (unsigned)((2 * AS_STAGE) + stage * BS_STAGE) * 4u;
#pragma unroll
        for (int it = 0; it < 4; it++) {
            int f   = tid + it * 256;
            int row = f >> 3;
            int seg = f & 7;
            int grow = blockM + row;
            int sz = (grow < N_NODES) ? 16 : 0;
            cp_async16(as_base + (unsigned)(row * AS_STRIDE + seg * 4) * 4u,
                       A + (size_t)grow * IN_FEATS + k0 + seg * 4, sz);
        }
#pragma unroll
        for (int it = 0; it < 4; it++) {
            int f  = tid + it * 256;
            int kr = f >> 5;
            int cs = (f & 31) * 4;
            cp_async16(bs_base + (unsigned)(kr * BS_STRIDE + cs) * 4u,
                       B + (size_t)(k0 + kr) * HD + cs, 16);
        }
    };

    load_stage(0, 0);
    cp_commit();

    for (int i = 0; i < 8; i++) {
        const int stage = i & 1;
        if (i < 7) {
            load_stage(stage ^ 1, (i + 1) * 32);
            cp_commit();
            asm volatile("cp.async.wait_group 1;");
        } else {
            asm volatile("cp.async.wait_group 0;");
        }
        __syncthreads();

        const float* As_s = sm + stage * AS_STAGE;
        const float* Bs_s = sm + 2 * AS_STAGE + stage * BS_STAGE;

#pragma unroll
        for (int ks = 0; ks < 4; ks++) {
            const int kb = ks * 8;
            unsigned afrag[2][4];
#pragma unroll
            for (int ii = 0; ii < 2; ii++) {
                int r = wm * 32 + ii * 16;
                afrag[ii][0] = tf32_bits(As_s[(r + g    ) * AS_STRIDE + kb + c    ]);
                afrag[ii][1] = tf32_bits(As_s[(r + g + 8) * AS_STRIDE + kb + c    ]);
                afrag[ii][2] = tf32_bits(As_s[(r + g    ) * AS_STRIDE + kb + c + 4]);
                afrag[ii][3] = tf32_bits(As_s[(r + g + 8) * AS_STRIDE + kb + c + 4]);
            }
            const float4* b0p = (const float4*)(Bs_s + (kb + c    ) * BS_STRIDE
                                                + g * 16 + wn * 8);
            const float4* b1p = (const float4*)(Bs_s + (kb + c + 4) * BS_STRIDE
                                                + g * 16 + wn * 8);
            float4 b0a = b0p[0], b0b = b0p[1];
            float4 b1a = b1p[0], b1b = b1p[1];
            const float b0v[8] = {b0a.x, b0a.y, b0a.z, b0a.w,
                                  b0b.x, b0b.y, b0b.z, b0b.w};
            const float b1v[8] = {b1a.x, b1a.y, b1a.z, b1a.w,
                                  b1b.x, b1b.y, b1b.z, b1b.w};
#pragma unroll
            for (int j = 0; j < 8; j++) {
                unsigned b0 = __float_as_uint(b0v[j]);
                unsigned b1 = __float_as_uint(b1v[j]);
                mma_tf32(acc[0][j], afrag[0], b0, b1);
                mma_tf32(acc[1][j], afrag[1], b0, b1);
            }
        }
        __syncthreads();
    }

    // epilogue 1: store ft as fp16 ONLY (fp32 copy was dead — nothing read it)
#pragma unroll
    for (int i = 0; i < 2; i++) {
        int r0 = blockM + wm * 32 + i * 16 + g;
#pragma unroll
        for (int j = 0; j < 8; j++) {
            int cc = wn * 64 + j * 8 + c * 2;
            if (r0 < N_NODES)
                *(__half2*)(g_fth + (size_t)r0 * HD + cc) =
                    __floats2half2_rn(acc[i][j][0], acc[i][j][1]);
            if (r0 + 8 < N_NODES)
                *(__half2*)(g_fth + (size_t)(r0 + 8) * HD + cc) =
                    __floats2half2_rn(acc[i][j][2], acc[i][j][3]);
        }
    }

    // epilogue 2: el/er
    float elp[4][2], erp[4][2];
#pragma unroll
    for (int rs = 0; rs < 4; rs++)
#pragma unroll
        for (int hl = 0; hl < 2; hl++) { elp[rs][hl] = 0.f; erp[rs][hl] = 0.f; }
#pragma unroll
    for (int i = 0; i < 2; i++)
#pragma unroll
        for (int j = 0; j < 8; j++)
#pragma unroll
            for (int r = 0; r < 4; r++) {
                int col = wn * 64 + j * 8 + c * 2 + (r & 1);
                float wl = __ldg(attn_l + col);
                float wr = __ldg(attn_r + col);
                int rs = i * 2 + (r >> 1);
                elp[rs][j >> 2] += acc[i][j][r] * wl;
                erp[rs][j >> 2] += acc[i][j][r] * wr;
            }
#pragma unroll
    for (int rs = 0; rs < 4; rs++)
#pragma unroll
        for (int hl = 0; hl < 2; hl++) {
#pragma unroll
            for (int o = 1; o <= 2; o <<= 1) {
                elp[rs][hl] += __shfl_xor_sync(0xffffffffu, elp[rs][hl], o);
                erp[rs][hl] += __shfl_xor_sync(0xffffffffu, erp[rs][hl], o);
            }
        }
    if (c == 0) {
#pragma unroll
        for (int rs = 0; rs < 4; rs++) {
            int row = blockM + wm * 32 + (rs >> 1) * 16 + (rs & 1) * 8 + g;
            if (row < N_NODES) {
#pragma unroll
                for (int hl = 0; hl < 2; hl++) {
                    int h = wn * 2 + hl;
                    g_el[row * HEADS + h] = elp[rs][hl];
                    g_er[row * HEADS + h] = erp[rs][hl];
                }
            }
        }
    }
}

// -------- histogram (int4) + fused tf32 round + PERMUTE of W ----------------
__global__ void hist_kernel(const int* __restrict__ dst,
                            const float* __restrict__ W) {
    int i = blockIdx.x * blockDim.x + threadIdx.x;
    if (i < (IN_FEATS * HD) / 4) {
        float4 v = ((const float4*)W)[i];
        int k = (i * 4) / HD;
        int n = (i * 4) % HD;
        float vv[4] = {to_tf32(v.x), to_tf32(v.y), to_tf32(v.z), to_tf32(v.w)};
#pragma unroll
        for (int q = 0; q < 4; q++) {
            int nn = n + q;
            int p = (nn & 7) * 16 + ((nn >> 6) & 1) * 8 + ((nn >> 3) & 7);
            g_wt[k * HD + p] = vv[q];
        }
    }
    if (i >= N_EDGES / 4) return;
    int4 d = ((const int4*)dst)[i];
    atomicAdd(&G_COUNTS[d.x], 1);
    atomicAdd(&G_COUNTS[d.y], 1);
    atomicAdd(&G_COUNTS[d.z], 1);
    atomicAdd(&G_COUNTS[d.w], 1);
}

// ---- CSR scatter + softmax numerator (after gemm: el/er ready) --------------
__global__ void scatter_kernel(const int* __restrict__ src,
                               const int* __restrict__ dst) {
    int e = blockIdx.x * blockDim.x + threadIdx.x;
    if (e >= N_EDGES) return;
    int s = src[e], d = dst[e];
    float4 el4 = *(const float4*)(g_el + (size_t)s * HEADS);
    float4 er4 = *(const float4*)(g_er + (size_t)d * HEADS);
    float4 v;
    v.x = el4.x + er4.x; v.y = el4.y + er4.y;
    v.z = el4.z + er4.z; v.w = el4.w + er4.w;
    v.x = v.x > 0.f ? v.x : NEG_SLOPE * v.x;
    v.y = v.y > 0.f ? v.y : NEG_SLOPE * v.y;
    v.z = v.z > 0.f ? v.z : NEG_SLOPE * v.z;
    v.w = v.w > 0.f ? v.w : NEG_SLOPE * v.w;
    float4 ex4;
    ex4.x = __expf(v.x); ex4.y = __expf(v.y);
    ex4.z = __expf(v.z); ex4.w = __expf(v.w);
    int pos = atomicAdd(&g_cursor[d], 1);
    g_csr[pos] = ((unsigned long long)(unsigned)s << 32) | (unsigned)e;
    *(float4*)(g_e + (size_t)pos * HEADS) = ex4;
}

// ---- aggregation (round-15 version, validated): fp16 gathers, fp32 accum ----
__global__ __launch_bounds__(256, 6) void agg_fused_kernel(
    float* __restrict__ rst, float* __restrict__ a_out, int has_a)
{
    __shared__ float ex_s[8][32][4];   // [warp][edge-in-chunk][head]
    int warp = (blockIdx.x * blockDim.x + threadIdx.x) >> 5;
    int lane = threadIdx.x & 31;
    int wlocal = (threadIdx.x >> 5);
    if (warp >= N_NODES) return;
    const int h = lane >> 3;
    const int p0 = g_offsets[warp];
    const int p1 = g_offsets[warp + 1];
    const int deg = p1 - p0;

    if (deg == 0) {
        *(float4*)(rst + (size_t)warp * HD + lane * 4) =
            make_float4(0.f, 0.f, 0.f, 0.f);
        return;
    }

    float4 acc = make_float4(0.f, 0.f, 0.f, 0.f);
    float denh = 0.0f;
    const uint2* fhl = (const uint2*)g_fth + lane;  // lane's 4 halves of a row

    float4 ex4 = make_float4(0.f, 0.f, 0.f, 0.f);   // my edge, last chunk
    int eid = 0;

    for (int base = p0; base < p1; base += 32) {
        int p = base + lane;
        ex4 = make_float4(0.f, 0.f, 0.f, 0.f);
        int s = 0;
        if (p < p1) {
            unsigned long long pk = g_csr[p];
            s = (int)(pk >> 32);
            eid = (int)(unsigned)(pk & 0xffffffffULL);
            ex4 = *(const float4*)(g_e + (size_t)p * HEADS);   // coalesced
        }

        __syncwarp();
        *(float4*)&ex_s[wlocal][lane][0] = ex4;
        __syncwarp();

        int cnt = min(p1 - base, 32);
        for (int q0 = 0; q0 < cnt; q0 += 4) {
            int m = cnt - q0;
            uint2 u0, u1, u2, u3;
            int sq;
            sq = __shfl_sync(0xffffffffu, s, q0);
            u0 = fhl[(size_t)(unsigned)sq * 32u];
            if (m > 1) { sq = __shfl_sync(0xffffffffu, s, q0 + 1);
                         u1 = fhl[(size_t)(unsigned)sq * 32u]; }
            if (m > 2) { sq = __shfl_sync(0xffffffffu, s, q0 + 2);
                         u2 = fhl[(size_t)(unsigned)sq * 32u]; }
            if (m > 3) { sq = __shfl_sync(0xffffffffu, s, q0 + 3);
                         u3 = fhl[(size_t)(unsigned)sq * 32u]; }
            {
                float e0 = ex_s[wlocal][q0][h];
                denh += e0;
                float2 a0 = __half22float2(*(__half2*)&u0.x);
                float2 a1 = __half22float2(*(__half2*)&u0.y);
                acc.x += e0 * a0.x; acc.y += e0 * a0.y;
                acc.z += e0 * a1.x; acc.w += e0 * a1.y;
            }
            if (m > 1) {
                float e1 = ex_s[wlocal][q0 + 1][h];
                denh += e1;
                float2 a0 = __half22float2(*(__half2*)&u1.x);
                float2 a1 = __half22float2(*(__half2*)&u1.y);
                acc.x += e1 * a0.x; acc.y += e1 * a0.y;
                acc.z += e1 * a1.x; acc.w += e1 * a1.y;
            }
            if (m > 2) {
                float e2 = ex_s[wlocal][q0 + 2][h];
                denh += e2;
                float2 a0 = __half22float2(*(__half2*)&u2.x);
                float2 a1 = __half22float2(*(__half2*)&u2.y);
                acc.x += e2 * a0.x; acc.y += e2 * a0.y;
                acc.z += e2 * a1.x; acc.w += e2 * a1.y;
            }
            if (m > 3) {
                float e3 = ex_s[wlocal][q0 + 3][h];
                denh += e3;
                float2 a0 = __half22float2(*(__half2*)&u3.x);
                float2 a1 = __half22float2(*(__half2*)&u3.y);
                acc.x += e3 * a0.x; acc.y += e3 * a0.y;
                acc.z += e3 * a1.x; acc.w += e3 * a1.y;
            }
        }
    }

    float rdh = 1.0f / denh;
    acc.x *= rdh; acc.y *= rdh; acc.z *= rdh; acc.w *= rdh;
    *(float4*)(rst + (size_t)warp * HD + lane * 4) = acc;

    if (has_a) {
        float4 rd4;
        rd4.x = __shfl_sync(0xffffffffu, rdh, 0);
        rd4.y = __shfl_sync(0xffffffffu, rdh, 8);
        rd4.z = __shfl_sync(0xffffffffu, rdh, 16);
        rd4.w = __shfl_sync(0xffffffffu, rdh, 24);
        if (deg <= 32) {
            int p = p0 + lane;
            if (p < p1) {
                float4 a4 = make_float4(ex4.x * rd4.x, ex4.y * rd4.y,
                                        ex4.z * rd4.z, ex4.w * rd4.w);
                *(float4*)(a_out + (size_t)eid * HEADS) = a4;
            }
        } else {
            for (int p = p0 + lane; p < p1; p += 32) {
                float4 e4 = *(const float4*)(g_e + (size_t)p * HEADS);
                int e = (int)(unsigned)(g_csr[p] & 0xffffffffULL);
                float4 a4 = make_float4(e4.x * rd4.x, e4.y * rd4.y,
                                        e4.z * rd4.z, e4.w * rd4.w);
                *(float4*)(a_out + (size_t)e * HEADS) = a4;
            }
        }
    }
}

// ---------------- launch ------------------------------------------------------
extern "C" void kernel_launch(void* const* d_in, const int* in_sizes, int n_in,
                              void* d_out, int out_size)
{
    const float* feat   = (const float*)d_in[0];
    const float* W      = (const float*)d_in[1];
    const float* attn_l = (const float*)d_in[2];
    const float* attn_r = (const float*)d_in[3];
    const int*   src    = (const int*)d_in[4];
    const int*   dst    = (const int*)d_in[5];
    float* out = (float*)d_out;

    const int rst_elems = N_NODES * HD;
    const int has_a = (out_size >= rst_elems + N_EDGES * HEADS) ? 1 : 0;
    float* a_out = out + rst_elems;

    float* wt_dev;   cudaGetSymbolAddress((void**)&wt_dev, g_wt);
    int*   pool_dev; cudaGetSymbolAddress((void**)&pool_dev, g_pool);

    cudaFuncSetAttribute(gemm_tf32_kernel,
                         cudaFuncAttributeMaxDynamicSharedMemorySize,
                         GEMM_SMEM_BYTES);

    cudaMemsetAsync(pool_dev, 0, (N_NODES + 256) * sizeof(int));

    hist_kernel<<<(N_EDGES / 4 + 255) / 256, 256>>>(dst, W);

    gemm_tf32_kernel<<<GEMM_BLOCKS + SCAN_BLOCKS, 256, GEMM_SMEM_BYTES>>>(
        feat, wt_dev, attn_l, attn_r);

    scatter_kernel<<<(N_EDGES + 255) / 256, 256>>>(src, dst);

    agg_fused_kernel<<<(N_NODES * 32 + 255) / 256, 256>>>(out, a_out, has_a);
}

// round 17
// speedup vs baseline: 1.0745x; 1.0237x over previous
#include <cuda_runtime.h>
#include <cuda_bf16.h>
#include <cuda_fp16.h>
#include <math.h>

#define N_NODES 100000
#define N_EDGES 640000
#define IN_FEATS 256
#define HEADS 4
#define OUT_FEATS 32
#define HD (HEADS * OUT_FEATS)   // 128
#define NEG_SLOPE 0.2f

#define GEMM_BLOCKS ((N_NODES + 127) / 128)      // 782
#define SCAN_BLOCKS 98                           // ceil(100000/1024)

// GEMM smem geometry (floats)
#define AS_STRIDE 36
#define BS_STRIDE 132
#define AS_STAGE (128 * AS_STRIDE)
#define BS_STAGE (32 * BS_STRIDE)
#define GEMM_SMEM_BYTES ((2 * AS_STAGE + 2 * BS_STAGE) * 4)   // 70656 B

// ---------------- scratch (no allocs allowed) ----------------
// NOTE: __device__ globals are zero-initialized at module load. The kernels
// restore the zero state (counts zeroed by scan after reading; lookback
// states zeroed by scatter) so every graph replay starts from zeros without
// a memset.
__device__ __half   g_fth[(size_t)N_NODES * HD];     // fp16 ft (only ft copy)
__device__ float    g_el[N_NODES * HEADS];
__device__ float    g_er[N_NODES * HEADS];
__device__ float    g_e [(size_t)N_EDGES * HEADS];   // exp(logit), CSR order
__device__ float    g_wt[IN_FEATS * HD];             // tf32-rounded, permuted W
__device__ int      g_pool[N_NODES + 256];           // counts + scan states
__device__ int      g_offsets[N_NODES + 1];
__device__ int      g_cursor[N_NODES];
__device__ unsigned long long g_csr[N_EDGES];        // (src<<32)|edge_id

#define G_COUNTS (g_pool)
#define G_STATE  ((unsigned long long*)(g_pool + N_NODES))

// ---------------- helpers ----------------
__device__ __forceinline__ unsigned tf32_bits(float x) {
    unsigned u;
    asm("cvt.rna.tf32.f32 %0, %1;" : "=r"(u) : "f"(x));
    return u;
}
__device__ __forceinline__ float to_tf32(float x) {
    return __uint_as_float(tf32_bits(x));
}
__device__ __forceinline__ void cp_async16(unsigned smem, const void* gmem,
                                           int src_bytes) {
    asm volatile("cp.async.cg.shared.global [%0], [%1], 16, %2;"
                 :: "r"(smem), "l"(gmem), "r"(src_bytes));
}
__device__ __forceinline__ void cp_commit() {
    asm volatile("cp.async.commit_group;");
}
__device__ __forceinline__ void mma_tf32(float* d, const unsigned* a,
                                         unsigned b0, unsigned b1) {
    asm volatile(
        "mma.sync.aligned.m16n8k8.row.col.f32.tf32.tf32.f32 "
        "{%0,%1,%2,%3}, {%4,%5,%6,%7}, {%8,%9}, {%0,%1,%2,%3};"
        : "+f"(d[0]), "+f"(d[1]), "+f"(d[2]), "+f"(d[3])
        : "r"(a[0]), "r"(a[1]), "r"(a[2]), "r"(a[3]), "r"(b0), "r"(b1));
}

// ---------------- scan body (256 threads, 1024 items/block) ------------------
__device__ void scan_body(int b, int* smi) {
    const int t = threadIdx.x;
    const int lane = t & 31, w = t >> 5;
    const int base = b * 1024 + t * 4;

    int v0 = 0, v1 = 0, v2 = 0, v3 = 0;
    if (base + 3 < N_NODES) {
        int4 q = *(const int4*)(G_COUNTS + base);
        v0 = q.x; v1 = q.y; v2 = q.z; v3 = q.w;
        *(int4*)(G_COUNTS + base) = make_int4(0, 0, 0, 0);   // restore zeros
    } else {
        if (base + 0 < N_NODES) { v0 = G_COUNTS[base + 0]; G_COUNTS[base + 0] = 0; }
        if (base + 1 < N_NODES) { v1 = G_COUNTS[base + 1]; G_COUNTS[base + 1] = 0; }
        if (base + 2 < N_NODES) { v2 = G_COUNTS[base + 2]; G_COUNTS[base + 2] = 0; }
        if (base + 3 < N_NODES) { v3 = G_COUNTS[base + 3]; G_COUNTS[base + 3] = 0; }
    }
    int tsum = v0 + v1 + v2 + v3;
    int x = tsum;
#pragma unroll
    for (int o = 1; o < 32; o <<= 1) {
        int u = __shfl_up_sync(0xffffffffu, x, o);
        if (lane >= o) x += u;
    }
    if (lane == 31) smi[w] = x;
    __syncthreads();
    if (t < 8) {
        int acc = 0;
        for (int j = 0; j <= t; j++) acc += smi[j];
        smi[t + 16] = acc;
    }
    __syncthreads();
    int warp_off = (w > 0) ? smi[16 + w - 1] : 0;
    int total = smi[16 + 7];

    if (t == 0) {
        unsigned long long* st = G_STATE;
        int excl = 0;
        if (b == 0) {
            __threadfence();
            atomicExch(&st[0], (2ULL << 32) | (unsigned)total);
        } else {
            __threadfence();
            atomicExch(&st[b], (1ULL << 32) | (unsigned)total);
            for (int j = b - 1; j >= 0;) {
                unsigned long long sv;
                do { sv = atomicAdd(&st[j], 0ULL); } while ((sv >> 32) == 0ULL);
                excl += (int)(sv & 0xffffffffULL);
                if ((sv >> 32) == 2ULL) break;
                j--;
            }
            __threadfence();
            atomicExch(&st[b], (2ULL << 32) | (unsigned)(excl + total));
        }
        smi[8] = excl;
    }
    __syncthreads();
    int pre = smi[8] + warp_off + (x - tsum);

    int o0 = pre, o1 = pre + v0, o2 = pre + v0 + v1, o3 = pre + v0 + v1 + v2;
    if (base + 3 < N_NODES) {
        *(int4*)(g_offsets + base) = make_int4(o0, o1, o2, o3);
        *(int4*)(g_cursor  + base) = make_int4(o0, o1, o2, o3);
    } else {
        if (base + 0 < N_NODES) { g_offsets[base+0] = o0; g_cursor[base+0] = o0; }
        if (base + 1 < N_NODES) { g_offsets[base+1] = o1; g_cursor[base+1] = o1; }
        if (base + 2 < N_NODES) { g_offsets[base+2] = o2; g_cursor[base+2] = o2; }
        if (base + 3 < N_NODES) { g_offsets[base+3] = o3; g_cursor[base+3] = o3; }
    }
    if (b == 0 && t == 0) g_offsets[N_NODES] = N_EDGES;
}

// ---- GEMM (TF32 MMA, cp.async 2-stage) + el/er + fp16-only ft + scan -------
__global__ __launch_bounds__(256, 2) void gemm_tf32_kernel(
    const float* __restrict__ A, const float* __restrict__ B,
    const float* __restrict__ attn_l, const float* __restrict__ attn_r)
{
    extern __shared__ float sm[];
    if (blockIdx.x >= GEMM_BLOCKS) {
        scan_body(blockIdx.x - GEMM_BLOCKS, (int*)sm);
        return;
    }
    const unsigned sm_u32 = (unsigned)__cvta_generic_to_shared(sm);
    const int tid  = threadIdx.x;
    const int warp = tid >> 5, lane = tid & 31;
    const int wm = warp >> 1, wn = warp & 1;
    const int g = lane >> 2, c = lane & 3;
    const int blockM = blockIdx.x * 128;

    float acc[2][8][4];
#pragma unroll
    for (int i = 0; i < 2; i++)
#pragma unroll
        for (int j = 0; j < 8; j++)
#pragma unroll
            for (int r = 0; r < 4; r++) acc[i][j][r] = 0.0f;

    auto load_stage = [&](int stage, int k0) {
        unsigned as_base = sm_u32 + (unsigned)(stage * AS_STAGE) * 4u;
        unsigned bs_base = sm_u32 + (unsigned)((2 * AS_STAGE) + stage * BS_STAGE) * 4u;
#pragma unroll
        for (int it = 0; it < 4; it++) {
            int f   = tid + it * 256;
            int row = f >> 3;
            int seg = f & 7;
            int grow = blockM + row;
            int sz = (grow < N_NODES) ? 16 : 0;
            cp_async16(as_base + (unsigned)(row * AS_STRIDE + seg * 4) * 4u,
                       A + (size_t)grow * IN_FEATS + k0 + seg * 4, sz);
        }
#pragma unroll
        for (int it = 0; it < 4; it++) {
            int f  = tid + it * 256;
            int kr = f >> 5;
            int cs = (f & 31) * 4;
            cp_async16(bs_base + (unsigned)(kr * BS_STRIDE + cs) * 4u,
                       B + (size_t)(k0 + kr) * HD + cs, 16);
        }
    };

    load_stage(0, 0);
    cp_commit();

    for (int i = 0; i < 8; i++) {
        const int stage = i & 1;
        if (i < 7) {
            load_stage(stage ^ 1, (i + 1) * 32);
            cp_commit();
            asm volatile("cp.async.wait_group 1;");
        } else {
            asm volatile("cp.async.wait_group 0;");
        }
        __syncthreads();

        const float* As_s = sm + stage * AS_STAGE;
        const float* Bs_s = sm + 2 * AS_STAGE + stage * BS_STAGE;

#pragma unroll
        for (int ks = 0; ks < 4; ks++) {
            const int kb = ks * 8;
            unsigned afrag[2][4];
#pragma unroll
            for (int ii = 0; ii < 2; ii++) {
                int r = wm * 32 + ii * 16;
                afrag[ii][0] = tf32_bits(As_s[(r + g    ) * AS_STRIDE + kb + c    ]);
                afrag[ii][1] = tf32_bits(As_s[(r + g + 8) * AS_STRIDE + kb + c    ]);
                afrag[ii][2] = tf32_bits(As_s[(r + g    ) * AS_STRIDE + kb + c + 4]);
                afrag[ii][3] = tf32_bits(As_s[(r + g + 8) * AS_STRIDE + kb + c + 4]);
            }
            const float4* b0p = (const float4*)(Bs_s + (kb + c    ) * BS_STRIDE
                                                + g * 16 + wn * 8);
            const float4* b1p = (const float4*)(Bs_s + (kb + c + 4) * BS_STRIDE
                                                + g * 16 + wn * 8);
            float4 b0a = b0p[0], b0b = b0p[1];
            float4 b1a = b1p[0], b1b = b1p[1];
            const float b0v[8] = {b0a.x, b0a.y, b0a.z, b0a.w,
                                  b0b.x, b0b.y, b0b.z, b0b.w};
            const float b1v[8] = {b1a.x, b1a.y, b1a.z, b1a.w,
                                  b1b.x, b1b.y, b1b.z, b1b.w};
#pragma unroll
            for (int j = 0; j < 8; j++) {
                unsigned b0 = __float_as_uint(b0v[j]);
                unsigned b1 = __float_as_uint(b1v[j]);
                mma_tf32(acc[0][j], afrag[0], b0, b1);
                mma_tf32(acc[1][j], afrag[1], b0, b1);
            }
        }
        __syncthreads();
    }

    // epilogue 1: store ft as fp16 only
#pragma unroll
    for (int i = 0; i < 2; i++) {
        int r0 = blockM + wm * 32 + i * 16 + g;
#pragma unroll
        for (int j = 0; j < 8; j++) {
            int cc = wn * 64 + j * 8 + c * 2;
            if (r0 < N_NODES)
                *(__half2*)(g_fth + (size_t)r0 * HD + cc) =
                    __floats2half2_rn(acc[i][j][0], acc[i][j][1]);
            if (r0 + 8 < N_NODES)
                *(__half2*)(g_fth + (size_t)(r0 + 8) * HD + cc) =
                    __floats2half2_rn(acc[i][j][2], acc[i][j][3]);
        }
    }

    // epilogue 2: el/er
    float elp[4][2], erp[4][2];
#pragma unroll
    for (int rs = 0; rs < 4; rs++)
#pragma unroll
        for (int hl = 0; hl < 2; hl++) { elp[rs][hl] = 0.f; erp[rs][hl] = 0.f; }
#pragma unroll
    for (int i = 0; i < 2; i++)
#pragma unroll
        for (int j = 0; j < 8; j++)
#pragma unroll
            for (int r = 0; r < 4; r++) {
                int col = wn * 64 + j * 8 + c * 2 + (r & 1);
                float wl = __ldg(attn_l + col);
                float wr = __ldg(attn_r + col);
                int rs = i * 2 + (r >> 1);
                elp[rs][j >> 2] += acc[i][j][r] * wl;
                erp[rs][j >> 2] += acc[i][j][r] * wr;
            }
#pragma unroll
    for (int rs = 0; rs < 4; rs++)
#pragma unroll
        for (int hl = 0; hl < 2; hl++) {
#pragma unroll
            for (int o = 1; o <= 2; o <<= 1) {
                elp[rs][hl] += __shfl_xor_sync(0xffffffffu, elp[rs][hl], o);
                erp[rs][hl] += __shfl_xor_sync(0xffffffffu, erp[rs][hl], o);
            }
        }
    if (c == 0) {
#pragma unroll
        for (int rs = 0; rs < 4; rs++) {
            int row = blockM + wm * 32 + (rs >> 1) * 16 + (rs & 1) * 8 + g;
            if (row < N_NODES) {
#pragma unroll
                for (int hl = 0; hl < 2; hl++) {
                    int h = wn * 2 + hl;
                    g_el[row * HEADS + h] = elp[rs][hl];
                    g_er[row * HEADS + h] = erp[rs][hl];
                }
            }
        }
    }
}

// -------- histogram (int4) + fused tf32 round + PERMUTE of W ----------------
__global__ void hist_kernel(const int* __restrict__ dst,
                            const float* __restrict__ W) {
    int i = blockIdx.x * blockDim.x + threadIdx.x;
    if (i < (IN_FEATS * HD) / 4) {
        float4 v = ((const float4*)W)[i];
        int k = (i * 4) / HD;
        int n = (i * 4) % HD;
        float vv[4] = {to_tf32(v.x), to_tf32(v.y), to_tf32(v.z), to_tf32(v.w)};
#pragma unroll
        for (int q = 0; q < 4; q++) {
            int nn = n + q;
            int p = (nn & 7) * 16 + ((nn >> 6) & 1) * 8 + ((nn >> 3) & 7);
            g_wt[k * HD + p] = vv[q];
        }
    }
    if (i >= N_EDGES / 4) return;
    int4 d = ((const int4*)dst)[i];
    atomicAdd(&G_COUNTS[d.x], 1);
    atomicAdd(&G_COUNTS[d.y], 1);
    atomicAdd(&G_COUNTS[d.z], 1);
    atomicAdd(&G_COUNTS[d.w], 1);
}

// ---- CSR scatter + softmax numerator (after gemm: el/er ready) --------------
// Also restores the scan lookback states to zero for the next graph replay
// (all scan blocks completed in the previous launch).
__global__ void scatter_kernel(const int* __restrict__ src,
                               const int* __restrict__ dst) {
    if (blockIdx.x == 0 && threadIdx.x < SCAN_BLOCKS)
        G_STATE[threadIdx.x] = 0ULL;
    int e = blockIdx.x * blockDim.x + threadIdx.x;
    if (e >= N_EDGES) return;
    int s = src[e], d = dst[e];
    float4 el4 = *(const float4*)(g_el + (size_t)s * HEADS);
    float4 er4 = *(const float4*)(g_er + (size_t)d * HEADS);
    float4 v;
    v.x = el4.x + er4.x; v.y = el4.y + er4.y;
    v.z = el4.z + er4.z; v.w = el4.w + er4.w;
    v.x = v.x > 0.f ? v.x : NEG_SLOPE * v.x;
    v.y = v.y > 0.f ? v.y : NEG_SLOPE * v.y;
    v.z = v.z > 0.f ? v.z : NEG_SLOPE * v.z;
    v.w = v.w > 0.f ? v.w : NEG_SLOPE * v.w;
    float4 ex4;
    ex4.x = __expf(v.x); ex4.y = __expf(v.y);
    ex4.z = __expf(v.z); ex4.w = __expf(v.w);
    int pos = atomicAdd(&g_cursor[d], 1);
    g_csr[pos] = ((unsigned long long)(unsigned)s << 32) | (unsigned)e;
    *(float4*)(g_e + (size_t)pos * HEADS) = ex4;
}

// ---- aggregation: fp16 gathers, fp32 accum; branch-free full groups --------
__global__ __launch_bounds__(256, 6) void agg_fused_kernel(
    float* __restrict__ rst, float* __restrict__ a_out, int has_a)
{
    __shared__ float ex_s[8][32][4];   // [warp][edge-in-chunk][head]
    int warp = (blockIdx.x * blockDim.x + threadIdx.x) >> 5;
    int lane = threadIdx.x & 31;
    int wlocal = (threadIdx.x >> 5);
    if (warp >= N_NODES) return;
    const int h = lane >> 3;
    const int p0 = g_offsets[warp];
    const int p1 = g_offsets[warp + 1];
    const int deg = p1 - p0;

    if (deg == 0) {
        *(float4*)(rst + (size_t)warp * HD + lane * 4) =
            make_float4(0.f, 0.f, 0.f, 0.f);
        return;
    }

    float4 acc = make_float4(0.f, 0.f, 0.f, 0.f);
    float denh = 0.0f;
    const uint2* fhl = (const uint2*)g_fth + lane;

    float4 ex4 = make_float4(0.f, 0.f, 0.f, 0.f);   // my edge, last chunk
    int eid = 0;

    for (int base = p0; base < p1; base += 32) {
        int p = base + lane;
        ex4 = make_float4(0.f, 0.f, 0.f, 0.f);
        int s = 0;
        if (p < p1) {
            unsigned long long pk = g_csr[p];
            s = (int)(pk >> 32);
            eid = (int)(unsigned)(pk & 0xffffffffULL);
            ex4 = *(const float4*)(g_e + (size_t)p * HEADS);   // coalesced
        }

        __syncwarp();
        *(float4*)&ex_s[wlocal][lane][0] = ex4;
        __syncwarp();

        const int cnt  = min(p1 - base, 32);
        const int full = cnt & ~3;
        int q0 = 0;
        for (; q0 < full; q0 += 4) {              // branch-free full groups
            uint2 u0, u1, u2, u3;
            int sq;
            sq = __shfl_sync(0xffffffffu, s, q0);
            u0 = fhl[(size_t)(unsigned)sq * 32u];
            sq = __shfl_sync(0xffffffffu, s, q0 + 1);
            u1 = fhl[(size_t)(unsigned)sq * 32u];
            sq = __shfl_sync(0xffffffffu, s, q0 + 2);
            u2 = fhl[(size_t)(unsigned)sq * 32u];
            sq = __shfl_sync(0xffffffffu, s, q0 + 3);
            u3 = fhl[(size_t)(unsigned)sq * 32u];

            float e0 = ex_s[wlocal][q0    ][h];
            float e1 = ex_s[wlocal][q0 + 1][h];
            float e2 = ex_s[wlocal][q0 + 2][h];
            float e3 = ex_s[wlocal][q0 + 3][h];
            denh += e0 + e1 + e2 + e3;
            float2 a0, a1;
            a0 = __half22float2(*(__half2*)&u0.x);
            a1 = __half22float2(*(__half2*)&u0.y);
            acc.x += e0 * a0.x; acc.y += e0 * a0.y;
            acc.z += e0 * a1.x; acc.w += e0 * a1.y;
            a0 = __half22float2(*(__half2*)&u1.x);
            a1 = __half22float2(*(__half2*)&u1.y);
            acc.x += e1 * a0.x; acc.y += e1 * a0.y;
            acc.z += e1 * a1.x; acc.w += e1 * a1.y;
            a0 = __half22float2(*(__half2*)&u2.x);
            a1 = __half22float2(*(__half2*)&u2.y);
            acc.x += e2 * a0.x; acc.y += e2 * a0.y;
            acc.z += e2 * a1.x; acc.w += e2 * a1.y;
            a0 = __half22float2(*(__half2*)&u3.x);
            a1 = __half22float2(*(__half2*)&u3.y);
            acc.x += e3 * a0.x; acc.y += e3 * a0.y;
            acc.z += e3 * a1.x; acc.w += e3 * a1.y;
        }
        for (; q0 < cnt; q0++) {                  // remainder (0-3 edges)
            int sq = __shfl_sync(0xffffffffu, s, q0);
            uint2 u = fhl[(size_t)(unsigned)sq * 32u];
            float e = ex_s[wlocal][q0][h];
            denh += e;
            float2 a0 = __half22float2(*(__half2*)&u.x);
            float2 a1 = __half22float2(*(__half2*)&u.y);
            acc.x += e * a0.x; acc.y += e * a0.y;
            acc.z += e * a1.x; acc.w += e * a1.y;
        }
    }

    float rdh = 1.0f / denh;
    acc.x *= rdh; acc.y *= rdh; acc.z *= rdh; acc.w *= rdh;
    *(float4*)(rst + (size_t)warp * HD + lane * 4) = acc;

    if (has_a) {
        float4 rd4;
        rd4.x = __shfl_sync(0xffffffffu, rdh, 0);
        rd4.y = __shfl_sync(0xffffffffu, rdh, 8);
        rd4.z = __shfl_sync(0xffffffffu, rdh, 16);
        rd4.w = __shfl_sync(0xffffffffu, rdh, 24);
        if (deg <= 32) {
            int p = p0 + lane;
            if (p < p1) {
                float4 a4 = make_float4(ex4.x * rd4.x, ex4.y * rd4.y,
                                        ex4.z * rd4.z, ex4.w * rd4.w);
                *(float4*)(a_out + (size_t)eid * HEADS) = a4;
            }
        } else {
            for (int p = p0 + lane; p < p1; p += 32) {
                float4 e4 = *(const float4*)(g_e + (size_t)p * HEADS);
                int e = (int)(unsigned)(g_csr[p] & 0xffffffffULL);
                float4 a4 = make_float4(e4.x * rd4.x, e4.y * rd4.y,
                                        e4.z * rd4.z, e4.w * rd4.w);
                *(float4*)(a_out + (size_t)e * HEADS) = a4;
            }
        }
    }
}

// ---------------- launch ------------------------------------------------------
extern "C" void kernel_launch(void* const* d_in, const int* in_sizes, int n_in,
                              void* d_out, int out_size)
{
    const float* feat   = (const float*)d_in[0];
    const float* W      = (const float*)d_in[1];
    const float* attn_l = (const float*)d_in[2];
    const float* attn_r = (const float*)d_in[3];
    const int*   src    = (const int*)d_in[4];
    const int*   dst    = (const int*)d_in[5];
    float* out = (float*)d_out;

    const int rst_elems = N_NODES * HD;
    const int has_a = (out_size >= rst_elems + N_EDGES * HEADS) ? 1 : 0;
    float* a_out = out + rst_elems;

    float* wt_dev;   cudaGetSymbolAddress((void**)&wt_dev, g_wt);

    cudaFuncSetAttribute(gemm_tf32_kernel,
                         cudaFuncAttributeMaxDynamicSharedMemorySize,
                         GEMM_SMEM_BYTES);

    // no memset: counts/states are zero at load and restored to zero by the
    // kernels themselves each run (scan zeroes counts, scatter zeroes states).

    hist_kernel<<<(N_EDGES / 4 + 255) / 256, 256>>>(dst, W);

    gemm_tf32_kernel<<<GEMM_BLOCKS + SCAN_BLOCKS, 256, GEMM_SMEM_BYTES>>>(
        feat, wt_dev, attn_l, attn_r);

    scatter_kernel<<<(N_EDGES + 255) / 256, 256>>>(src, dst);

    agg_fused_kernel<<<(N_NODES * 32 + 255) / 256, 256>>>(out, a_out, has_a);
}